// round 14
// baseline (speedup 1.0000x reference)
#include <cuda_runtime.h>
#include <cuda_bf16.h>
#include <math.h>

// ---------------- problem constants ----------------
#define SEQ   2048
#define DIMC  1024
#define HEADS 16
#define KVH   4
#define HD    64
#define KVDIM 256
#define WIN   64
#define NGLOB 32
#define TQ    32
#define SCALE 0.125f

// ---------------- scratch ----------------
__device__ float g_Q[SEQ * DIMC];
__device__ float g_K[SEQ * KVDIM];
__device__ float g_V[SEQ * KVDIM];
__device__ float g_A[SEQ * DIMC];
__device__ float g_Xc [SEQ * DIMC];        // tf32-rounded x
__device__ float g_WqT[DIMC * DIMC];       // transposed tf32 weights [N][K]
__device__ float g_WkT[KVDIM * DIMC];
__device__ float g_WvT[KVDIM * DIMC];
__device__ float g_WoT[DIMC * DIMC];

// ---------------- helpers ----------------
__device__ __forceinline__ unsigned f2tf32(float f) {
    unsigned r; asm("cvt.rna.tf32.f32 %0, %1;" : "=r"(r) : "f"(f)); return r;
}
__device__ __forceinline__ float tf32r(float f) { return __uint_as_float(f2tf32(f)); }

__device__ __forceinline__ void mma_tf32(float* c, const unsigned* a, const unsigned* b) {
    asm volatile(
        "mma.sync.aligned.m16n8k8.row.col.f32.tf32.tf32.f32 "
        "{%0,%1,%2,%3}, {%4,%5,%6,%7}, {%8,%9}, {%0,%1,%2,%3};"
        : "+f"(c[0]), "+f"(c[1]), "+f"(c[2]), "+f"(c[3])
        : "r"(a[0]), "r"(a[1]), "r"(a[2]), "r"(a[3]), "r"(b[0]), "r"(b[1]));
}

__device__ __forceinline__ void ldsm4(unsigned* r, unsigned saddr) {
    asm volatile("ldmatrix.sync.aligned.m8n8.x4.shared.b16 {%0,%1,%2,%3}, [%4];"
                 : "=r"(r[0]), "=r"(r[1]), "=r"(r[2]), "=r"(r[3]) : "r"(saddr));
}
__device__ __forceinline__ void ldsm2(unsigned* r, unsigned saddr) {
    asm volatile("ldmatrix.sync.aligned.m8n8.x2.shared.b16 {%0,%1}, [%2];"
                 : "=r"(r[0]), "=r"(r[1]) : "r"(saddr));
}

__device__ __forceinline__ void cp16(float* dst, const float* src) {
    unsigned s = (unsigned)__cvta_generic_to_shared(dst);
    asm volatile("cp.async.cg.shared.global [%0], [%1], 16;" :: "r"(s), "l"(src));
}
#define CP_COMMIT() asm volatile("cp.async.commit_group;")
#define CP_WAIT0()  asm volatile("cp.async.wait_group 0;")

__device__ __forceinline__ unsigned smem_u32(const void* p) {
    return (unsigned)__cvta_generic_to_shared(p);
}

// ---------------- geometry A: BK=32 (qkv) ----------------
#define BM 128
#define BN 64
#define BK32 32
#define RSTR32 36
#define A32_FL (BM * RSTR32)               // 4608
#define B32_FL (BN * RSTR32)               // 2304
#define ST32_FL (A32_FL + B32_FL)          // 6912
#define ST32_BYTES (ST32_FL * 4)           // 27648
#define QKV_SMEM (2 * ST32_BYTES)          // 55296
#define NCH32 (DIMC / BK32)                // 32

// ---------------- geometry B: BK=64 (wo) ----------------
#define BK64 64
#define RSTR64 68
#define A64_FL (BM * RSTR64)               // 8704
#define B64_FL (BN * RSTR64)               // 4352
#define ST64_FL (A64_FL + B64_FL)          // 13056
#define ST64_BYTES (ST64_FL * 4)           // 52224
#define WO_SMEM (2 * ST64_BYTES)           // 104448
#define NCH64 (DIMC / BK64)                // 16

// =================================================================
// Convert: x elementwise tf32-round; weights -> transposed tf32 [N][K].
// =================================================================
__global__ __launch_bounds__(256)
void cvt_all(const float4* __restrict__ x, const float* __restrict__ wq,
             const float* __restrict__ wk, const float* __restrict__ wv,
             const float* __restrict__ wo,
             float4* __restrict__ xc, float* __restrict__ wqT,
             float* __restrict__ wkT, float* __restrict__ wvT,
             float* __restrict__ woT)
{
    __shared__ float s[32][33];
    const int tid = threadIdx.x;
    if (blockIdx.x < 2048) {
        int i = blockIdx.x * 256 + tid;
        float4 v = x[i];
        v.x = tf32r(v.x); v.y = tf32r(v.y); v.z = tf32r(v.z); v.w = tf32r(v.w);
        xc[i] = v;
        return;
    }
    int b = blockIdx.x - 2048;
    const float* W; float* WT; int N;
    if (b < 1024)       { W = wq; WT = wqT; N = DIMC; }
    else if (b < 1280)  { b -= 1024; W = wk; WT = wkT; N = KVDIM; }
    else if (b < 1536)  { b -= 1280; W = wv; WT = wvT; N = KVDIM; }
    else                { b -= 1536; W = wo; WT = woT; N = DIMC; }
    const int ntile = N / 32;
    const int n0 = (b % ntile) * 32;
    const int k0 = (b / ntile) * 32;
    const int c = tid & 31, r0 = tid >> 5;
#pragma unroll
    for (int rr = 0; rr < 4; rr++) {
        int r = r0 + rr * 8;
        s[r][c] = tf32r(W[(size_t)(k0 + r) * N + n0 + c]);
    }
    __syncthreads();
#pragma unroll
    for (int rr = 0; rr < 4; rr++) {
        int r = r0 + rr * 8;
        WT[(size_t)(n0 + r) * DIMC + k0 + c] = s[c][r];
    }
}

// =================================================================
// Geometry A: BK=32 tile (R12-proven, used by qkv)
// =================================================================
__device__ __forceinline__ void mma_tile32(const float* __restrict__ A,
                                           const float* __restrict__ BT,
                                           float* __restrict__ C,
                                           int ldc, int by, float* sm)
{
    const int tid  = threadIdx.x;
    const int lane = tid & 31, warp = tid >> 5;
    const int wm = (warp >> 1) * 32;
    const int wn = (warp & 1) * 32;
    const int grp = lane >> 2, ctg = lane & 3;

    float acc[2][4][4];
#pragma unroll
    for (int i = 0; i < 2; i++)
#pragma unroll
        for (int j = 0; j < 4; j++)
#pragma unroll
            for (int r = 0; r < 4; r++) acc[i][j][r] = 0.f;

    const float* Abase = A + (size_t)(by * BM) * DIMC;

    auto load_chunk = [&](int c, int s) {
        float* as = sm + s * ST32_FL;
        float* bs = as + A32_FL;
        const int k0 = c * BK32;
#pragma unroll
        for (int i = 0; i < 4; i++) {
            int idx = tid + i * 256;
            int r = idx >> 3, g = idx & 7;
            cp16(as + r * RSTR32 + g * 4, Abase + (size_t)r * DIMC + k0 + g * 4);
        }
#pragma unroll
        for (int i = 0; i < 2; i++) {
            int idx = tid + i * 256;
            int n = idx >> 3, g = idx & 7;
            cp16(bs + n * RSTR32 + g * 4, BT + (size_t)n * DIMC + k0 + g * 4);
        }
    };

    const unsigned aOff = (unsigned)(((wm + (lane & 15)) * RSTR32 + (lane >> 4) * 4) * 4);
    const unsigned bOff = (unsigned)(A32_FL * 4 +
        ((wn + ((lane >> 4) << 3) + (lane & 7)) * RSTR32 + ((lane >> 3) & 1) * 4) * 4);
    const unsigned sb = smem_u32(sm);

    load_chunk(0, 0); CP_COMMIT();

#pragma unroll 2
    for (int c = 0; c < NCH32; c++) {
        const int s = c & 1;
        CP_WAIT0();
        __syncthreads();
        if (c + 1 < NCH32) {
            load_chunk(c + 1, s ^ 1);
            CP_COMMIT();
        }

        const unsigned stb = sb + (unsigned)(s * ST32_BYTES);
        const unsigned aA = stb + aOff;
        const unsigned bA = stb + bOff;
#pragma unroll
        for (int ks = 0; ks < 4; ks++) {
            unsigned a0[4], a1[4], b0[4], b1[4];
            ldsm4(a0, aA + ks * 32);
            ldsm4(a1, aA + 2304 + ks * 32);
            ldsm4(b0, bA + ks * 32);
            ldsm4(b1, bA + 2304 + ks * 32);
            mma_tf32(acc[0][0], a0, &b0[0]);
            mma_tf32(acc[0][1], a0, &b0[2]);
            mma_tf32(acc[0][2], a0, &b1[0]);
            mma_tf32(acc[0][3], a0, &b1[2]);
            mma_tf32(acc[1][0], a1, &b0[0]);
            mma_tf32(acc[1][1], a1, &b0[2]);
            mma_tf32(acc[1][2], a1, &b1[0]);
            mma_tf32(acc[1][3], a1, &b1[2]);
        }
    }

#pragma unroll
    for (int mi = 0; mi < 2; mi++) {
        const int row = by * BM + wm + mi * 16 + grp;
#pragma unroll
        for (int ni = 0; ni < 4; ni++) {
            const int col = wn + ni * 8 + 2 * ctg;
            *(float2*)(C + (size_t)row * ldc + col) =
                make_float2(acc[mi][ni][0], acc[mi][ni][1]);
            *(float2*)(C + (size_t)(row + 8) * ldc + col) =
                make_float2(acc[mi][ni][2], acc[mi][ni][3]);
        }
    }
}

// =================================================================
// Geometry B: BK=64 tile (R13-proven, used by wo)
// =================================================================
__device__ __forceinline__ void mma_tile64(const float* __restrict__ A,
                                           const float* __restrict__ BT,
                                           float* __restrict__ C,
                                           int ldc, int by, float* sm)
{
    const int tid  = threadIdx.x;
    const int lane = tid & 31, warp = tid >> 5;
    const int wm = (warp >> 1) * 32;
    const int wn = (warp & 1) * 32;
    const int grp = lane >> 2, ctg = lane & 3;

    float acc[2][4][4];
#pragma unroll
    for (int i = 0; i < 2; i++)
#pragma unroll
        for (int j = 0; j < 4; j++)
#pragma unroll
            for (int r = 0; r < 4; r++) acc[i][j][r] = 0.f;

    const float* Abase = A + (size_t)(by * BM) * DIMC;

    auto load_chunk = [&](int c, int s) {
        float* as = sm + s * ST64_FL;
        float* bs = as + A64_FL;
        const int k0 = c * BK64;
#pragma unroll
        for (int i = 0; i < 8; i++) {
            int idx = tid + i * 256;
            int r = idx >> 4, g = idx & 15;
            cp16(as + r * RSTR64 + g * 4, Abase + (size_t)r * DIMC + k0 + g * 4);
        }
#pragma unroll
        for (int i = 0; i < 4; i++) {
            int idx = tid + i * 256;
            int n = idx >> 4, g = idx & 15;
            cp16(bs + n * RSTR64 + g * 4, BT + (size_t)n * DIMC + k0 + g * 4);
        }
    };

    const unsigned aOff = (unsigned)(((wm + (lane & 15)) * RSTR64 + (lane >> 4) * 4) * 4);
    const unsigned bOff = (unsigned)(A64_FL * 4 +
        ((wn + ((lane >> 4) << 3) + (lane & 7)) * RSTR64 + ((lane >> 3) & 1) * 4) * 4);
    const unsigned sb = smem_u32(sm);

    load_chunk(0, 0); CP_COMMIT();

#pragma unroll 1
    for (int c = 0; c < NCH64; c++) {
        const int s = c & 1;
        CP_WAIT0();
        __syncthreads();
        if (c + 1 < NCH64) {
            load_chunk(c + 1, s ^ 1);
            CP_COMMIT();
        }

        const unsigned stb = sb + (unsigned)(s * ST64_BYTES);
        const unsigned aA = stb + aOff;
        const unsigned bA = stb + bOff;
#pragma unroll
        for (int ks = 0; ks < 8; ks++) {
            unsigned a0[4], a1[4], b0[4], b1[4];
            ldsm4(a0, aA + ks * 32);
            ldsm4(a1, aA + 4352 + ks * 32);
            ldsm4(b0, bA + ks * 32);
            ldsm4(b1, bA + 4352 + ks * 32);
            mma_tf32(acc[0][0], a0, &b0[0]);
            mma_tf32(acc[0][1], a0, &b0[2]);
            mma_tf32(acc[0][2], a0, &b1[0]);
            mma_tf32(acc[0][3], a0, &b1[2]);
            mma_tf32(acc[1][0], a1, &b0[0]);
            mma_tf32(acc[1][1], a1, &b0[2]);
            mma_tf32(acc[1][2], a1, &b1[0]);
            mma_tf32(acc[1][3], a1, &b1[2]);
        }
    }

#pragma unroll
    for (int mi = 0; mi < 2; mi++) {
        const int row = by * BM + wm + mi * 16 + grp;
#pragma unroll
        for (int ni = 0; ni < 4; ni++) {
            const int col = wn + ni * 8 + 2 * ctg;
            *(float2*)(C + (size_t)row * ldc + col) =
                make_float2(acc[mi][ni][0], acc[mi][ni][1]);
            *(float2*)(C + (size_t)(row + 8) * ldc + col) =
                make_float2(acc[mi][ni][2], acc[mi][ni][3]);
        }
    }
}

__global__ __launch_bounds__(256, 3)
void tf32_qkv(const float* __restrict__ Xc,
              const float* __restrict__ WqT, const float* __restrict__ WkT,
              const float* __restrict__ WvT,
              float* __restrict__ Q, float* __restrict__ Ko, float* __restrict__ Vo)
{
    extern __shared__ float sm[];
    const int bx = blockIdx.x;
    const float* BT; float* C; int ld;
    if (bx < 16)      { BT = WqT + (size_t)bx * 64 * DIMC;        C = Q  + bx * 64;        ld = DIMC;  }
    else if (bx < 20) { BT = WkT + (size_t)(bx - 16) * 64 * DIMC; C = Ko + (bx - 16) * 64; ld = KVDIM; }
    else              { BT = WvT + (size_t)(bx - 20) * 64 * DIMC; C = Vo + (bx - 20) * 64; ld = KVDIM; }
    mma_tile32(Xc, BT, C, ld, blockIdx.y, sm);
}

__global__ __launch_bounds__(256, 2)
void tf32_wo(const float* __restrict__ Ac, const float* __restrict__ WoT,
             float* __restrict__ Out)
{
    extern __shared__ float sm[];
    mma_tile64(Ac, WoT + (size_t)blockIdx.x * 64 * DIMC, Out + blockIdx.x * 64,
               DIMC, blockIdx.y, sm);
}

// =================================================================
// Tensorized attention (unchanged). Grid (64,16), 256 thr, 92KB.
// =================================================================
#define AT_QS 0
#define AT_KL 2176
#define AT_KG 8704
#define AT_VT 10880
#define AT_P  19328
#define ATTN_SMEM (23552 * 4)

__global__ __launch_bounds__(256)
void attn_mma(const float* __restrict__ Q, const float* __restrict__ K,
              const float* __restrict__ V, float* __restrict__ O)
{
    extern __shared__ float sm[];
    const int h = blockIdx.y, kvh = h >> 2, q0 = blockIdx.x * TQ;
    const int tid = threadIdx.x, lane = tid & 31, warp = tid >> 5;
    const float slope = exp2f(-0.5f * (float)(h + 1));

    for (int i = tid; i < 32 * 16; i += 256) {
        int q = i >> 4, d4 = i & 15;
        float4 v = *(const float4*)&Q[(size_t)(q0 + q) * DIMC + h * HD + d4 * 4];
        v.x = tf32r(v.x); v.y = tf32r(v.y); v.z = tf32r(v.z); v.w = tf32r(v.w);
        *(float4*)&sm[AT_QS + q * 68 + d4 * 4] = v;
    }
    for (int i = tid; i < 96 * 16; i += 256) {
        int r = i >> 4, d4 = i & 15;
        int key = q0 - 64 + r;
        float4 v = make_float4(0.f, 0.f, 0.f, 0.f);
        if (key >= 0) {
            v = *(const float4*)&K[(size_t)key * KVDIM + kvh * HD + d4 * 4];
            v.x = tf32r(v.x); v.y = tf32r(v.y); v.z = tf32r(v.z); v.w = tf32r(v.w);
        }
        *(float4*)&sm[AT_KL + r * 68 + d4 * 4] = v;
    }
    for (int i = tid; i < 32 * 16; i += 256) {
        int g = i >> 4, d4 = i & 15;
        float4 v = *(const float4*)&K[(size_t)(g * WIN) * KVDIM + kvh * HD + d4 * 4];
        v.x = tf32r(v.x); v.y = tf32r(v.y); v.z = tf32r(v.z); v.w = tf32r(v.w);
        *(float4*)&sm[AT_KG + g * 68 + d4 * 4] = v;
    }
    for (int i = tid; i < 128 * 16; i += 256) {
        int col = i >> 4, d4 = i & 15;
        int key; bool valid;
        if (col < 96) { key = q0 - 64 + col; valid = (key >= 0); }
        else          { key = (col - 96) * WIN; valid = true; }
        float4 v = make_float4(0.f, 0.f, 0.f, 0.f);
        if (valid) {
            v = *(const float4*)&V[(size_t)key * KVDIM + kvh * HD + d4 * 4];
            v.x = tf32r(v.x); v.y = tf32r(v.y); v.z = tf32r(v.z); v.w = tf32r(v.w);
        }
        sm[AT_VT + (d4 * 4 + 0) * 132 + col] = v.x;
        sm[AT_VT + (d4 * 4 + 1) * 132 + col] = v.y;
        sm[AT_VT + (d4 * 4 + 2) * 132 + col] = v.z;
        sm[AT_VT + (d4 * 4 + 3) * 132 + col] = v.w;
    }
    __syncthreads();

    const unsigned sb = smem_u32(sm);
    const int m0  = (warp >> 2) * 16;
    const int wnl = (warp & 3) * 24;
    const int wng = (warp & 3) * 8;
    const int ln  = lane & 15;
    const int grp = lane >> 2, ctg = lane & 3;

    {
        const unsigned aQ  = sb + (unsigned)((AT_QS + (m0 + ln) * 68 + (lane >> 4) * 4) * 4);
        const unsigned bKl = sb + (unsigned)((AT_KL + (wnl + ((lane >> 4) << 3) + (lane & 7)) * 68 + ((lane >> 3) & 1) * 4) * 4);
        const unsigned bK2 = sb + (unsigned)((AT_KL + (wnl + 16 + (ln & 7)) * 68 + ((ln >> 3) & 1) * 4) * 4);
        const unsigned bKg = sb + (unsigned)((AT_KG + (wng + (ln & 7)) * 68 + ((ln >> 3) & 1) * 4) * 4);

        float accl[3][4], accg[4];
#pragma unroll
        for (int f = 0; f < 3; f++)
#pragma unroll
            for (int r = 0; r < 4; r++) accl[f][r] = 0.f;
#pragma unroll
        for (int r = 0; r < 4; r++) accg[r] = 0.f;

#pragma unroll
        for (int ks = 0; ks < 8; ks++) {
            unsigned a[4], b01[4], b2[2], bg[2];
            ldsm4(a, aQ + ks * 32);
            ldsm4(b01, bKl + ks * 32);
            ldsm2(b2, bK2 + ks * 32);
            ldsm2(bg, bKg + ks * 32);
            mma_tf32(accl[0], a, &b01[0]);
            mma_tf32(accl[1], a, &b01[2]);
            mma_tf32(accl[2], a, b2);
            mma_tf32(accg, a, bg);
        }
        const int row = m0 + grp;
#pragma unroll
        for (int f = 0; f < 3; f++) {
            int col = wnl + f * 8 + 2 * ctg;
            *(float2*)&sm[AT_P + row * 132 + col]       = make_float2(accl[f][0], accl[f][1]);
            *(float2*)&sm[AT_P + (row + 8) * 132 + col] = make_float2(accl[f][2], accl[f][3]);
        }
        int colg = 96 + wng + 2 * ctg;
        *(float2*)&sm[AT_P + row * 132 + colg]       = make_float2(accg[0], accg[1]);
        *(float2*)&sm[AT_P + (row + 8) * 132 + colg] = make_float2(accg[2], accg[3]);
    }
    __syncthreads();

    for (int q = warp * 4; q < warp * 4 + 4; q++) {
        float l[3]; bool vld[3];
        float m = -3.0e38f;
#pragma unroll
        for (int t = 0; t < 3; t++) {
            int r = lane + t * 32;
            vld[t] = (r >= q) && (r <= q + 64) && (q0 - 64 + r >= 0);
            l[t] = vld[t] ? sm[AT_P + q * 132 + r] * SCALE + (float)(r - q - 64) * slope
                          : -3.0e38f;
            m = fmaxf(m, l[t]);
        }
#pragma unroll
        for (int o = 16; o; o >>= 1) m = fmaxf(m, __shfl_xor_sync(~0u, m, o));
        float e[3], sum = 0.f;
#pragma unroll
        for (int t = 0; t < 3; t++) {
            e[t] = vld[t] ? __expf(l[t] - m) : 0.f;
            sum += e[t];
        }
#pragma unroll
        for (int o = 16; o; o >>= 1) sum += __shfl_xor_sync(~0u, sum, o);
        float inv = 1.f / sum;
#pragma unroll
        for (int t = 0; t < 3; t++)
            sm[AT_P + q * 132 + lane + t * 32] = tf32r(e[t] * inv);

        float gl = sm[AT_P + q * 132 + 96 + lane] * SCALE;
        float mg = gl;
#pragma unroll
        for (int o = 16; o; o >>= 1) mg = fmaxf(mg, __shfl_xor_sync(~0u, mg, o));
        float ge = __expf(gl - mg);
        float gs = ge;
#pragma unroll
        for (int o = 16; o; o >>= 1) gs += __shfl_xor_sync(~0u, gs, o);
        sm[AT_P + q * 132 + 96 + lane] = tf32r(ge / gs);
    }
    __syncthreads();

    {
        const int n0 = (warp & 3) * 16;
        const unsigned aP = sb + (unsigned)((AT_P + (m0 + ln) * 132 + (lane >> 4) * 4) * 4);
        const unsigned bV = sb + (unsigned)((AT_VT + (n0 + ((lane >> 4) << 3) + (lane & 7)) * 132 + ((lane >> 3) & 1) * 4) * 4);

        float acco[2][4];
#pragma unroll
        for (int f = 0; f < 2; f++)
#pragma unroll
            for (int r = 0; r < 4; r++) acco[f][r] = 0.f;

#pragma unroll
        for (int ks = 0; ks < 16; ks++) {
            unsigned a[4], b[4];
            ldsm4(a, aP + ks * 32);
            ldsm4(b, bV + ks * 32);
            mma_tf32(acco[0], a, &b[0]);
            mma_tf32(acco[1], a, &b[2]);
        }

        const int row = m0 + grp;
#pragma unroll
        for (int f = 0; f < 2; f++) {
            int col = h * HD + n0 + f * 8 + 2 * ctg;
            *(float2*)&O[(size_t)(q0 + row) * DIMC + col] =
                make_float2(tf32r(acco[f][0]), tf32r(acco[f][1]));
            *(float2*)&O[(size_t)(q0 + row + 8) * DIMC + col] =
                make_float2(tf32r(acco[f][2]), tf32r(acco[f][3]));
        }
    }
}

// =================================================================
extern "C" void kernel_launch(void* const* d_in, const int* in_sizes, int n_in,
                              void* d_out, int out_size)
{
    const float* x  = (const float*)d_in[0];
    const float* Wq = (const float*)d_in[1];
    const float* Wk = (const float*)d_in[2];
    const float* Wv = (const float*)d_in[3];
    const float* Wo = (const float*)d_in[4];
    float* out = (float*)d_out;

    float *gQ, *gK, *gV, *gA, *gXc, *gWqT, *gWkT, *gWvT, *gWoT;
    cudaGetSymbolAddress((void**)&gQ,  g_Q);
    cudaGetSymbolAddress((void**)&gK,  g_K);
    cudaGetSymbolAddress((void**)&gV,  g_V);
    cudaGetSymbolAddress((void**)&gA,  g_A);
    cudaGetSymbolAddress((void**)&gXc, g_Xc);
    cudaGetSymbolAddress((void**)&gWqT, g_WqT);
    cudaGetSymbolAddress((void**)&gWkT, g_WkT);
    cudaGetSymbolAddress((void**)&gWvT, g_WvT);
    cudaGetSymbolAddress((void**)&gWoT, g_WoT);

    cudaFuncSetAttribute(tf32_qkv, cudaFuncAttributeMaxDynamicSharedMemorySize, QKV_SMEM);
    cudaFuncSetAttribute(tf32_wo,  cudaFuncAttributeMaxDynamicSharedMemorySize, WO_SMEM);
    cudaFuncSetAttribute(attn_mma, cudaFuncAttributeMaxDynamicSharedMemorySize, ATTN_SMEM);

    cvt_all<<<4608, 256>>>((const float4*)x, Wq, Wk, Wv, Wo,
                           (float4*)gXc, gWqT, gWkT, gWvT, gWoT);
    tf32_qkv<<<dim3(24, 16), 256, QKV_SMEM>>>(gXc, gWqT, gWkT, gWvT, gQ, gK, gV);
    attn_mma<<<dim3(SEQ / TQ, HEADS), 256, ATTN_SMEM>>>(gQ, gK, gV, gA);
    tf32_wo<<<dim3(16, 16), 256, WO_SMEM>>>(gA, gWoT, out);
}

// round 15
// speedup vs baseline: 1.1713x; 1.1713x over previous
#include <cuda_runtime.h>
#include <cuda_bf16.h>
#include <math.h>

// ---------------- problem constants ----------------
#define SEQ   2048
#define DIMC  1024
#define HEADS 16
#define KVH   4
#define HD    64
#define KVDIM 256
#define WIN   64
#define NGLOB 32
#define TQ    32
#define SCALE 0.125f

// ---------------- scratch ----------------
__device__ float g_Q[SEQ * DIMC];
__device__ float g_K[SEQ * KVDIM];
__device__ float g_V[SEQ * KVDIM];
__device__ float g_A[SEQ * DIMC];
__device__ float g_Xc [SEQ * DIMC];        // tf32-rounded x
__device__ float g_WqT[DIMC * DIMC];       // transposed tf32 weights [N][K]
__device__ float g_WkT[KVDIM * DIMC];
__device__ float g_WvT[KVDIM * DIMC];
__device__ float g_WoT[DIMC * DIMC];

// ---------------- helpers ----------------
__device__ __forceinline__ unsigned f2tf32(float f) {
    unsigned r; asm("cvt.rna.tf32.f32 %0, %1;" : "=r"(r) : "f"(f)); return r;
}
__device__ __forceinline__ float tf32r(float f) { return __uint_as_float(f2tf32(f)); }

__device__ __forceinline__ void mma_tf32(float* c, const unsigned* a, const unsigned* b) {
    asm volatile(
        "mma.sync.aligned.m16n8k8.row.col.f32.tf32.tf32.f32 "
        "{%0,%1,%2,%3}, {%4,%5,%6,%7}, {%8,%9}, {%0,%1,%2,%3};"
        : "+f"(c[0]), "+f"(c[1]), "+f"(c[2]), "+f"(c[3])
        : "r"(a[0]), "r"(a[1]), "r"(a[2]), "r"(a[3]), "r"(b[0]), "r"(b[1]));
}

__device__ __forceinline__ void ldsm4(unsigned* r, unsigned saddr) {
    asm volatile("ldmatrix.sync.aligned.m8n8.x4.shared.b16 {%0,%1,%2,%3}, [%4];"
                 : "=r"(r[0]), "=r"(r[1]), "=r"(r[2]), "=r"(r[3]) : "r"(saddr));
}
__device__ __forceinline__ void ldsm2(unsigned* r, unsigned saddr) {
    asm volatile("ldmatrix.sync.aligned.m8n8.x2.shared.b16 {%0,%1}, [%2];"
                 : "=r"(r[0]), "=r"(r[1]) : "r"(saddr));
}

__device__ __forceinline__ void cp16(float* dst, const float* src) {
    unsigned s = (unsigned)__cvta_generic_to_shared(dst);
    asm volatile("cp.async.cg.shared.global [%0], [%1], 16;" :: "r"(s), "l"(src));
}
__device__ __forceinline__ void cp16z(float* dst, const float* src, bool valid) {
    unsigned s = (unsigned)__cvta_generic_to_shared(dst);
    int sz = valid ? 16 : 0;
    asm volatile("cp.async.cg.shared.global [%0], [%1], 16, %2;"
                 :: "r"(s), "l"(src), "r"(sz));
}
#define CP_COMMIT() asm volatile("cp.async.commit_group;")
#define CP_WAIT0()  asm volatile("cp.async.wait_group 0;")

__device__ __forceinline__ unsigned smem_u32(const void* p) {
    return (unsigned)__cvta_generic_to_shared(p);
}

// ---------------- GEMM geometry (R12-proven: BK=32, 2-stage) ----------------
#define BM 128
#define BN 64
#define BK 32
#define RSTR 36
#define A_FL (BM * RSTR)               // 4608
#define B_FL (BN * RSTR)               // 2304
#define ST_FL (A_FL + B_FL)            // 6912
#define ST_BYTES (ST_FL * 4)           // 27648
#define GEMM_SMEM (2 * ST_BYTES)       // 55296
#define NCH (DIMC / BK)                // 32

// =================================================================
// Convert: x elementwise tf32-round; weights -> transposed tf32 [N][K].
// =================================================================
__global__ __launch_bounds__(256)
void cvt_all(const float4* __restrict__ x, const float* __restrict__ wq,
             const float* __restrict__ wk, const float* __restrict__ wv,
             const float* __restrict__ wo,
             float4* __restrict__ xc, float* __restrict__ wqT,
             float* __restrict__ wkT, float* __restrict__ wvT,
             float* __restrict__ woT)
{
    __shared__ float s[32][33];
    const int tid = threadIdx.x;
    if (blockIdx.x < 2048) {
        int i = blockIdx.x * 256 + tid;
        float4 v = x[i];
        v.x = tf32r(v.x); v.y = tf32r(v.y); v.z = tf32r(v.z); v.w = tf32r(v.w);
        xc[i] = v;
        return;
    }
    int b = blockIdx.x - 2048;
    const float* W; float* WT; int N;
    if (b < 1024)       { W = wq; WT = wqT; N = DIMC; }
    else if (b < 1280)  { b -= 1024; W = wk; WT = wkT; N = KVDIM; }
    else if (b < 1536)  { b -= 1280; W = wv; WT = wvT; N = KVDIM; }
    else                { b -= 1536; W = wo; WT = woT; N = DIMC; }
    const int ntile = N / 32;
    const int n0 = (b % ntile) * 32;
    const int k0 = (b / ntile) * 32;
    const int c = tid & 31, r0 = tid >> 5;
#pragma unroll
    for (int rr = 0; rr < 4; rr++) {
        int r = r0 + rr * 8;
        s[r][c] = tf32r(W[(size_t)(k0 + r) * N + n0 + c]);
    }
    __syncthreads();
#pragma unroll
    for (int rr = 0; rr < 4; rr++) {
        int r = r0 + rr * 8;
        WT[(size_t)(n0 + r) * DIMC + k0 + c] = s[c][r];
    }
}

// =================================================================
// 128x64 tf32 MMA tile (R12 geometry). ROUND: tf32-round outputs.
// =================================================================
template <bool ROUND>
__device__ __forceinline__ void mma_tile(const float* __restrict__ A,
                                         const float* __restrict__ BT,
                                         float* __restrict__ C,
                                         int ldc, int by, float* sm)
{
    const int tid  = threadIdx.x;
    const int lane = tid & 31, warp = tid >> 5;
    const int wm = (warp >> 1) * 32;
    const int wn = (warp & 1) * 32;
    const int grp = lane >> 2, ctg = lane & 3;

    float acc[2][4][4];
#pragma unroll
    for (int i = 0; i < 2; i++)
#pragma unroll
        for (int j = 0; j < 4; j++)
#pragma unroll
            for (int r = 0; r < 4; r++) acc[i][j][r] = 0.f;

    const float* Abase = A + (size_t)(by * BM) * DIMC;

    auto load_chunk = [&](int c, int s) {
        float* as = sm + s * ST_FL;
        float* bs = as + A_FL;
        const int k0 = c * BK;
#pragma unroll
        for (int i = 0; i < 4; i++) {
            int idx = tid + i * 256;
            int r = idx >> 3, g = idx & 7;
            cp16(as + r * RSTR + g * 4, Abase + (size_t)r * DIMC + k0 + g * 4);
        }
#pragma unroll
        for (int i = 0; i < 2; i++) {
            int idx = tid + i * 256;
            int n = idx >> 3, g = idx & 7;
            cp16(bs + n * RSTR + g * 4, BT + (size_t)n * DIMC + k0 + g * 4);
        }
    };

    const unsigned aOff = (unsigned)(((wm + (lane & 15)) * RSTR + (lane >> 4) * 4) * 4);
    const unsigned bOff = (unsigned)(A_FL * 4 +
        ((wn + ((lane >> 4) << 3) + (lane & 7)) * RSTR + ((lane >> 3) & 1) * 4) * 4);
    const unsigned sb = smem_u32(sm);

    load_chunk(0, 0); CP_COMMIT();

#pragma unroll 2
    for (int c = 0; c < NCH; c++) {
        const int s = c & 1;
        CP_WAIT0();
        __syncthreads();
        if (c + 1 < NCH) {
            load_chunk(c + 1, s ^ 1);
            CP_COMMIT();
        }

        const unsigned stb = sb + (unsigned)(s * ST_BYTES);
        const unsigned aA = stb + aOff;
        const unsigned bA = stb + bOff;
#pragma unroll
        for (int ks = 0; ks < 4; ks++) {
            unsigned a0[4], a1[4], b0[4], b1[4];
            ldsm4(a0, aA + ks * 32);
            ldsm4(a1, aA + 2304 + ks * 32);
            ldsm4(b0, bA + ks * 32);
            ldsm4(b1, bA + 2304 + ks * 32);
            mma_tf32(acc[0][0], a0, &b0[0]);
            mma_tf32(acc[0][1], a0, &b0[2]);
            mma_tf32(acc[0][2], a0, &b1[0]);
            mma_tf32(acc[0][3], a0, &b1[2]);
            mma_tf32(acc[1][0], a1, &b0[0]);
            mma_tf32(acc[1][1], a1, &b0[2]);
            mma_tf32(acc[1][2], a1, &b1[0]);
            mma_tf32(acc[1][3], a1, &b1[2]);
        }
    }

#pragma unroll
    for (int mi = 0; mi < 2; mi++) {
        const int row = by * BM + wm + mi * 16 + grp;
#pragma unroll
        for (int ni = 0; ni < 4; ni++) {
            const int col = wn + ni * 8 + 2 * ctg;
            float v0 = acc[mi][ni][0], v1 = acc[mi][ni][1];
            float v2 = acc[mi][ni][2], v3 = acc[mi][ni][3];
            if (ROUND) { v0 = tf32r(v0); v1 = tf32r(v1); v2 = tf32r(v2); v3 = tf32r(v3); }
            *(float2*)(C + (size_t)row * ldc + col)       = make_float2(v0, v1);
            *(float2*)(C + (size_t)(row + 8) * ldc + col) = make_float2(v2, v3);
        }
    }
}

__global__ __launch_bounds__(256, 3)
void tf32_qkv(const float* __restrict__ Xc,
              const float* __restrict__ WqT, const float* __restrict__ WkT,
              const float* __restrict__ WvT,
              float* __restrict__ Q, float* __restrict__ Ko, float* __restrict__ Vo)
{
    extern __shared__ float sm[];
    const int bx = blockIdx.x;
    const float* BT; float* C; int ld;
    if (bx < 16)      { BT = WqT + (size_t)bx * 64 * DIMC;        C = Q  + bx * 64;        ld = DIMC;  }
    else if (bx < 20) { BT = WkT + (size_t)(bx - 16) * 64 * DIMC; C = Ko + (bx - 16) * 64; ld = KVDIM; }
    else              { BT = WvT + (size_t)(bx - 20) * 64 * DIMC; C = Vo + (bx - 20) * 64; ld = KVDIM; }
    mma_tile<true>(Xc, BT, C, ld, blockIdx.y, sm);   // rounded outputs for attention
}

__global__ __launch_bounds__(256, 3)
void tf32_wo(const float* __restrict__ Ac, const float* __restrict__ WoT,
             float* __restrict__ Out)
{
    extern __shared__ float sm[];
    mma_tile<false>(Ac, WoT + (size_t)blockIdx.x * 64 * DIMC, Out + blockIdx.x * 64,
                    DIMC, blockIdx.y, sm);
}

// =================================================================
// Tensorized attention, 2 query heads per block (shared KV).
// Grid (64, 8), 256 threads, 103KB dyn smem -> 2 CTAs/SM.
// Q/K/V arrive pre-tf32-rounded from the qkv epilogue (pure cp.async stage).
// Smem (floats): Qs[2][32][68] | Kl[96][68] | Kg[32][68] | Vt[64][132] | P[32][132]
// =================================================================
#define AT_QS 0
#define AT_KL 4352
#define AT_KG 10880
#define AT_VT 13056
#define AT_P  21504
#define ATTN_SMEM (25728 * 4)

__global__ __launch_bounds__(256)
void attn_mma(const float* __restrict__ Q, const float* __restrict__ K,
              const float* __restrict__ V, float* __restrict__ O)
{
    extern __shared__ float sm[];
    const int kvh = blockIdx.y >> 1;
    const int h0  = blockIdx.y * 2;          // first of 2 heads (same kv group)
    const int q0  = blockIdx.x * TQ;
    const int tid = threadIdx.x, lane = tid & 31, warp = tid >> 5;
    const float4 z4 = make_float4(0.f, 0.f, 0.f, 0.f);

    // ---- cp.async stage: Q (2 heads), local K, global K ----
    for (int i = tid; i < 1024; i += 256) {
        int hh = i >> 9, rem = i & 511, q = rem >> 4, d4 = rem & 15;
        cp16(&sm[AT_QS + hh * 2176 + q * 68 + d4 * 4],
             &Q[(size_t)(q0 + q) * DIMC + (h0 + hh) * HD + d4 * 4]);
    }
    for (int i = tid; i < 1536; i += 256) {
        int r = i >> 4, d4 = i & 15;
        int key = q0 - 64 + r;
        cp16z(&sm[AT_KL + r * 68 + d4 * 4],
              &K[(size_t)max(key, 0) * KVDIM + kvh * HD + d4 * 4], key >= 0);
    }
    for (int i = tid; i < 512; i += 256) {
        int g = i >> 4, d4 = i & 15;
        cp16(&sm[AT_KG + g * 68 + d4 * 4],
             &K[(size_t)(g * WIN) * KVDIM + kvh * HD + d4 * 4]);
    }
    CP_COMMIT();

    // ---- V transposed (manual scatter; values pre-rounded) ----
    for (int i = tid; i < 2048; i += 256) {
        int col = i >> 4, d4 = i & 15;
        int key; bool valid;
        if (col < 96) { key = q0 - 64 + col; valid = (key >= 0); }
        else          { key = (col - 96) * WIN; valid = true; }
        float4 v = valid ? *(const float4*)&V[(size_t)key * KVDIM + kvh * HD + d4 * 4] : z4;
        sm[AT_VT + (d4 * 4 + 0) * 132 + col] = v.x;
        sm[AT_VT + (d4 * 4 + 1) * 132 + col] = v.y;
        sm[AT_VT + (d4 * 4 + 2) * 132 + col] = v.z;
        sm[AT_VT + (d4 * 4 + 3) * 132 + col] = v.w;
    }
    CP_WAIT0();
    __syncthreads();

    const unsigned sb = smem_u32(sm);
    const int m0  = (warp >> 2) * 16;
    const int wnl = (warp & 3) * 24;
    const int wng = (warp & 3) * 8;
    const int ln  = lane & 15;
    const int grp = lane >> 2, ctg = lane & 3;

#pragma unroll 1
    for (int hh = 0; hh < 2; hh++) {
        const int h = h0 + hh;
        const float slope = exp2f(-0.5f * (float)(h + 1));

        // ---- score MMAs: local 32x96, global 32x32, K=64 ----
        {
            const unsigned aQ  = sb + (unsigned)((AT_QS + hh * 2176 + (m0 + ln) * 68 + (lane >> 4) * 4) * 4);
            const unsigned bKl = sb + (unsigned)((AT_KL + (wnl + ((lane >> 4) << 3) + (lane & 7)) * 68 + ((lane >> 3) & 1) * 4) * 4);
            const unsigned bK2 = sb + (unsigned)((AT_KL + (wnl + 16 + (ln & 7)) * 68 + ((ln >> 3) & 1) * 4) * 4);
            const unsigned bKg = sb + (unsigned)((AT_KG + (wng + (ln & 7)) * 68 + ((ln >> 3) & 1) * 4) * 4);

            float accl[3][4], accg[4];
#pragma unroll
            for (int f = 0; f < 3; f++)
#pragma unroll
                for (int r = 0; r < 4; r++) accl[f][r] = 0.f;
#pragma unroll
            for (int r = 0; r < 4; r++) accg[r] = 0.f;

#pragma unroll
            for (int ks = 0; ks < 8; ks++) {
                unsigned a[4], b01[4], b2[2], bg[2];
                ldsm4(a, aQ + ks * 32);
                ldsm4(b01, bKl + ks * 32);
                ldsm2(b2, bK2 + ks * 32);
                ldsm2(bg, bKg + ks * 32);
                mma_tf32(accl[0], a, &b01[0]);
                mma_tf32(accl[1], a, &b01[2]);
                mma_tf32(accl[2], a, b2);
                mma_tf32(accg, a, bg);
            }
            const int row = m0 + grp;
#pragma unroll
            for (int f = 0; f < 3; f++) {
                int col = wnl + f * 8 + 2 * ctg;
                *(float2*)&sm[AT_P + row * 132 + col]       = make_float2(accl[f][0], accl[f][1]);
                *(float2*)&sm[AT_P + (row + 8) * 132 + col] = make_float2(accl[f][2], accl[f][3]);
            }
            int colg = 96 + wng + 2 * ctg;
            *(float2*)&sm[AT_P + row * 132 + colg]       = make_float2(accg[0], accg[1]);
            *(float2*)&sm[AT_P + (row + 8) * 132 + colg] = make_float2(accg[2], accg[3]);
        }
        __syncthreads();

        // ---- softmaxes (warp per 4 rows), write tf32-rounded probs ----
        for (int q = warp * 4; q < warp * 4 + 4; q++) {
            float l[3]; bool vld[3];
            float m = -3.0e38f;
#pragma unroll
            for (int t = 0; t < 3; t++) {
                int r = lane + t * 32;
                vld[t] = (r >= q) && (r <= q + 64) && (q0 - 64 + r >= 0);
                l[t] = vld[t] ? sm[AT_P + q * 132 + r] * SCALE + (float)(r - q - 64) * slope
                              : -3.0e38f;
                m = fmaxf(m, l[t]);
            }
#pragma unroll
            for (int o = 16; o; o >>= 1) m = fmaxf(m, __shfl_xor_sync(~0u, m, o));
            float e[3], sum = 0.f;
#pragma unroll
            for (int t = 0; t < 3; t++) {
                e[t] = vld[t] ? __expf(l[t] - m) : 0.f;
                sum += e[t];
            }
#pragma unroll
            for (int o = 16; o; o >>= 1) sum += __shfl_xor_sync(~0u, sum, o);
            float inv = 1.f / sum;
#pragma unroll
            for (int t = 0; t < 3; t++)
                sm[AT_P + q * 132 + lane + t * 32] = tf32r(e[t] * inv);

            float gl = sm[AT_P + q * 132 + 96 + lane] * SCALE;
            float mg = gl;
#pragma unroll
            for (int o = 16; o; o >>= 1) mg = fmaxf(mg, __shfl_xor_sync(~0u, mg, o));
            float ge = __expf(gl - mg);
            float gs = ge;
#pragma unroll
            for (int o = 16; o; o >>= 1) gs += __shfl_xor_sync(~0u, gs, o);
            sm[AT_P + q * 132 + 96 + lane] = tf32r(ge / gs);
        }
        __syncthreads();

        // ---- PV: 32x64, K=128 (local||global) ----
        {
            const int n0 = (warp & 3) * 16;
            const unsigned aP = sb + (unsigned)((AT_P + (m0 + ln) * 132 + (lane >> 4) * 4) * 4);
            const unsigned bV = sb + (unsigned)((AT_VT + (n0 + ((lane >> 4) << 3) + (lane & 7)) * 132 + ((lane >> 3) & 1) * 4) * 4);

            float acco[2][4];
#pragma unroll
            for (int f = 0; f < 2; f++)
#pragma unroll
                for (int r = 0; r < 4; r++) acco[f][r] = 0.f;

#pragma unroll
            for (int ks = 0; ks < 16; ks++) {
                unsigned a[4], b[4];
                ldsm4(a, aP + ks * 32);
                ldsm4(b, bV + ks * 32);
                mma_tf32(acco[0], a, &b[0]);
                mma_tf32(acco[1], a, &b[2]);
            }

            const int row = m0 + grp;
#pragma unroll
            for (int f = 0; f < 2; f++) {
                int col = h * HD + n0 + f * 8 + 2 * ctg;
                *(float2*)&O[(size_t)(q0 + row) * DIMC + col] =
                    make_float2(tf32r(acco[f][0]), tf32r(acco[f][1]));
                *(float2*)&O[(size_t)(q0 + row + 8) * DIMC + col] =
                    make_float2(tf32r(acco[f][2]), tf32r(acco[f][3]));
            }
        }
        if (hh == 0) __syncthreads();   // P reused by next head
    }
}

// =================================================================
extern "C" void kernel_launch(void* const* d_in, const int* in_sizes, int n_in,
                              void* d_out, int out_size)
{
    const float* x  = (const float*)d_in[0];
    const float* Wq = (const float*)d_in[1];
    const float* Wk = (const float*)d_in[2];
    const float* Wv = (const float*)d_in[3];
    const float* Wo = (const float*)d_in[4];
    float* out = (float*)d_out;

    float *gQ, *gK, *gV, *gA, *gXc, *gWqT, *gWkT, *gWvT, *gWoT;
    cudaGetSymbolAddress((void**)&gQ,  g_Q);
    cudaGetSymbolAddress((void**)&gK,  g_K);
    cudaGetSymbolAddress((void**)&gV,  g_V);
    cudaGetSymbolAddress((void**)&gA,  g_A);
    cudaGetSymbolAddress((void**)&gXc, g_Xc);
    cudaGetSymbolAddress((void**)&gWqT, g_WqT);
    cudaGetSymbolAddress((void**)&gWkT, g_WkT);
    cudaGetSymbolAddress((void**)&gWvT, g_WvT);
    cudaGetSymbolAddress((void**)&gWoT, g_WoT);

    cudaFuncSetAttribute(tf32_qkv, cudaFuncAttributeMaxDynamicSharedMemorySize, GEMM_SMEM);
    cudaFuncSetAttribute(tf32_wo,  cudaFuncAttributeMaxDynamicSharedMemorySize, GEMM_SMEM);
    cudaFuncSetAttribute(attn_mma, cudaFuncAttributeMaxDynamicSharedMemorySize, ATTN_SMEM);

    cvt_all<<<4608, 256>>>((const float4*)x, Wq, Wk, Wv, Wo,
                           (float4*)gXc, gWqT, gWkT, gWvT, gWoT);
    tf32_qkv<<<dim3(24, 16), 256, GEMM_SMEM>>>(gXc, gWqT, gWkT, gWvT, gQ, gK, gV);
    attn_mma<<<dim3(SEQ / TQ, HEADS / 2), 256, ATTN_SMEM>>>(gQ, gK, gV, gA);
    tf32_wo<<<dim3(16, 16), 256, GEMM_SMEM>>>(gA, gWoT, out);
}

// round 16
// speedup vs baseline: 1.1748x; 1.0030x over previous
#include <cuda_runtime.h>
#include <cuda_bf16.h>
#include <math.h>

// ---------------- problem constants ----------------
#define SEQ   2048
#define DIMC  1024
#define HEADS 16
#define KVH   4
#define HD    64
#define KVDIM 256
#define WIN   64
#define NGLOB 32
#define TQ    32
#define SCALE 0.125f

// ---------------- scratch ----------------
__device__ float g_Q[SEQ * DIMC];
__device__ float g_K[SEQ * KVDIM];
__device__ float g_V[SEQ * KVDIM];
__device__ float g_A[SEQ * DIMC];
__device__ float g_WqT[DIMC * DIMC];       // transposed tf32 weights [N][K]
__device__ float g_WkT[KVDIM * DIMC];
__device__ float g_WvT[KVDIM * DIMC];
__device__ float g_WoT[DIMC * DIMC];

// ---------------- helpers ----------------
__device__ __forceinline__ unsigned f2tf32(float f) {
    unsigned r; asm("cvt.rna.tf32.f32 %0, %1;" : "=r"(r) : "f"(f)); return r;
}
__device__ __forceinline__ float tf32r(float f) { return __uint_as_float(f2tf32(f)); }

__device__ __forceinline__ void mma_tf32(float* c, const unsigned* a, const unsigned* b) {
    asm volatile(
        "mma.sync.aligned.m16n8k8.row.col.f32.tf32.tf32.f32 "
        "{%0,%1,%2,%3}, {%4,%5,%6,%7}, {%8,%9}, {%0,%1,%2,%3};"
        : "+f"(c[0]), "+f"(c[1]), "+f"(c[2]), "+f"(c[3])
        : "r"(a[0]), "r"(a[1]), "r"(a[2]), "r"(a[3]), "r"(b[0]), "r"(b[1]));
}

__device__ __forceinline__ void ldsm4(unsigned* r, unsigned saddr) {
    asm volatile("ldmatrix.sync.aligned.m8n8.x4.shared.b16 {%0,%1,%2,%3}, [%4];"
                 : "=r"(r[0]), "=r"(r[1]), "=r"(r[2]), "=r"(r[3]) : "r"(saddr));
}
__device__ __forceinline__ void ldsm2(unsigned* r, unsigned saddr) {
    asm volatile("ldmatrix.sync.aligned.m8n8.x2.shared.b16 {%0,%1}, [%2];"
                 : "=r"(r[0]), "=r"(r[1]) : "r"(saddr));
}

__device__ __forceinline__ void cp16(float* dst, const float* src) {
    unsigned s = (unsigned)__cvta_generic_to_shared(dst);
    asm volatile("cp.async.cg.shared.global [%0], [%1], 16;" :: "r"(s), "l"(src));
}
__device__ __forceinline__ void cp16z(float* dst, const float* src, bool valid) {
    unsigned s = (unsigned)__cvta_generic_to_shared(dst);
    int sz = valid ? 16 : 0;
    asm volatile("cp.async.cg.shared.global [%0], [%1], 16, %2;"
                 :: "r"(s), "l"(src), "r"(sz));
}
#define CP_COMMIT() asm volatile("cp.async.commit_group;")
#define CP_WAIT0()  asm volatile("cp.async.wait_group 0;")

__device__ __forceinline__ unsigned smem_u32(const void* p) {
    return (unsigned)__cvta_generic_to_shared(p);
}

// ---------------- geometry A: BK=32 (qkv) ----------------
#define BM 128
#define BN 64
#define BK32 32
#define RSTR32 36
#define A32_FL (BM * RSTR32)
#define B32_FL (BN * RSTR32)
#define ST32_FL (A32_FL + B32_FL)
#define ST32_BYTES (ST32_FL * 4)           // 27648
#define QKV_SMEM (2 * ST32_BYTES)          // 55296
#define NCH32 (DIMC / BK32)                // 32

// ---------------- geometry B: BK=64 (wo) ----------------
#define BK64 64
#define RSTR64 68
#define A64_FL (BM * RSTR64)
#define B64_FL (BN * RSTR64)
#define ST64_FL (A64_FL + B64_FL)
#define ST64_BYTES (ST64_FL * 4)           // 52224
#define WO_SMEM (2 * ST64_BYTES)           // 104448
#define NCH64 (DIMC / BK64)                // 16

// =================================================================
// Convert: weights -> transposed tf32 [N][K]. 2560 blocks.
// =================================================================
__global__ __launch_bounds__(256)
void cvt_w(const float* __restrict__ wq, const float* __restrict__ wk,
           const float* __restrict__ wv, const float* __restrict__ wo,
           float* __restrict__ wqT, float* __restrict__ wkT,
           float* __restrict__ wvT, float* __restrict__ woT)
{
    __shared__ float s[32][33];
    const int tid = threadIdx.x;
    int b = blockIdx.x;
    const float* W; float* WT; int N;
    if (b < 1024)       { W = wq; WT = wqT; N = DIMC; }
    else if (b < 1280)  { b -= 1024; W = wk; WT = wkT; N = KVDIM; }
    else if (b < 1536)  { b -= 1280; W = wv; WT = wvT; N = KVDIM; }
    else                { b -= 1536; W = wo; WT = woT; N = DIMC; }
    const int ntile = N / 32;
    const int n0 = (b % ntile) * 32;
    const int k0 = (b / ntile) * 32;
    const int c = tid & 31, r0 = tid >> 5;
#pragma unroll
    for (int rr = 0; rr < 4; rr++) {
        int r = r0 + rr * 8;
        s[r][c] = tf32r(W[(size_t)(k0 + r) * N + n0 + c]);
    }
    __syncthreads();
#pragma unroll
    for (int rr = 0; rr < 4; rr++) {
        int r = r0 + rr * 8;
        WT[(size_t)(n0 + r) * DIMC + k0 + c] = s[c][r];
    }
}

// =================================================================
// Geometry A: BK=32 tile (qkv). ROUND rounds outputs to tf32 values.
// =================================================================
template <bool ROUND>
__device__ __forceinline__ void mma_tile32(const float* __restrict__ A,
                                           const float* __restrict__ BT,
                                           float* __restrict__ C,
                                           int ldc, int by, float* sm)
{
    const int tid  = threadIdx.x;
    const int lane = tid & 31, warp = tid >> 5;
    const int wm = (warp >> 1) * 32;
    const int wn = (warp & 1) * 32;
    const int grp = lane >> 2, ctg = lane & 3;

    float acc[2][4][4];
#pragma unroll
    for (int i = 0; i < 2; i++)
#pragma unroll
        for (int j = 0; j < 4; j++)
#pragma unroll
            for (int r = 0; r < 4; r++) acc[i][j][r] = 0.f;

    const float* Abase = A + (size_t)(by * BM) * DIMC;

    auto load_chunk = [&](int c, int s) {
        float* as = sm + s * ST32_FL;
        float* bs = as + A32_FL;
        const int k0 = c * BK32;
#pragma unroll
        for (int i = 0; i < 4; i++) {
            int idx = tid + i * 256;
            int r = idx >> 3, g = idx & 7;
            cp16(as + r * RSTR32 + g * 4, Abase + (size_t)r * DIMC + k0 + g * 4);
        }
#pragma unroll
        for (int i = 0; i < 2; i++) {
            int idx = tid + i * 256;
            int n = idx >> 3, g = idx & 7;
            cp16(bs + n * RSTR32 + g * 4, BT + (size_t)n * DIMC + k0 + g * 4);
        }
    };

    const unsigned aOff = (unsigned)(((wm + (lane & 15)) * RSTR32 + (lane >> 4) * 4) * 4);
    const unsigned bOff = (unsigned)(A32_FL * 4 +
        ((wn + ((lane >> 4) << 3) + (lane & 7)) * RSTR32 + ((lane >> 3) & 1) * 4) * 4);
    const unsigned sb = smem_u32(sm);

    load_chunk(0, 0); CP_COMMIT();

#pragma unroll 2
    for (int c = 0; c < NCH32; c++) {
        const int s = c & 1;
        CP_WAIT0();
        __syncthreads();
        if (c + 1 < NCH32) {
            load_chunk(c + 1, s ^ 1);
            CP_COMMIT();
        }

        const unsigned stb = sb + (unsigned)(s * ST32_BYTES);
        const unsigned aA = stb + aOff;
        const unsigned bA = stb + bOff;
#pragma unroll
        for (int ks = 0; ks < 4; ks++) {
            unsigned a0[4], a1[4], b0[4], b1[4];
            ldsm4(a0, aA + ks * 32);
            ldsm4(a1, aA + 2304 + ks * 32);
            ldsm4(b0, bA + ks * 32);
            ldsm4(b1, bA + 2304 + ks * 32);
            mma_tf32(acc[0][0], a0, &b0[0]);
            mma_tf32(acc[0][1], a0, &b0[2]);
            mma_tf32(acc[0][2], a0, &b1[0]);
            mma_tf32(acc[0][3], a0, &b1[2]);
            mma_tf32(acc[1][0], a1, &b0[0]);
            mma_tf32(acc[1][1], a1, &b0[2]);
            mma_tf32(acc[1][2], a1, &b1[0]);
            mma_tf32(acc[1][3], a1, &b1[2]);
        }
    }

#pragma unroll
    for (int mi = 0; mi < 2; mi++) {
        const int row = by * BM + wm + mi * 16 + grp;
#pragma unroll
        for (int ni = 0; ni < 4; ni++) {
            const int col = wn + ni * 8 + 2 * ctg;
            float v0 = acc[mi][ni][0], v1 = acc[mi][ni][1];
            float v2 = acc[mi][ni][2], v3 = acc[mi][ni][3];
            if (ROUND) { v0 = tf32r(v0); v1 = tf32r(v1); v2 = tf32r(v2); v3 = tf32r(v3); }
            *(float2*)(C + (size_t)row * ldc + col)       = make_float2(v0, v1);
            *(float2*)(C + (size_t)(row + 8) * ldc + col) = make_float2(v2, v3);
        }
    }
}

// =================================================================
// Geometry B: BK=64 tile (wo; R13-proven 37.8us)
// =================================================================
__device__ __forceinline__ void mma_tile64(const float* __restrict__ A,
                                           const float* __restrict__ BT,
                                           float* __restrict__ C,
                                           int ldc, int by, float* sm)
{
    const int tid  = threadIdx.x;
    const int lane = tid & 31, warp = tid >> 5;
    const int wm = (warp >> 1) * 32;
    const int wn = (warp & 1) * 32;
    const int grp = lane >> 2, ctg = lane & 3;

    float acc[2][4][4];
#pragma unroll
    for (int i = 0; i < 2; i++)
#pragma unroll
        for (int j = 0; j < 4; j++)
#pragma unroll
            for (int r = 0; r < 4; r++) acc[i][j][r] = 0.f;

    const float* Abase = A + (size_t)(by * BM) * DIMC;

    auto load_chunk = [&](int c, int s) {
        float* as = sm + s * ST64_FL;
        float* bs = as + A64_FL;
        const int k0 = c * BK64;
#pragma unroll
        for (int i = 0; i < 8; i++) {
            int idx = tid + i * 256;
            int r = idx >> 4, g = idx & 15;
            cp16(as + r * RSTR64 + g * 4, Abase + (size_t)r * DIMC + k0 + g * 4);
        }
#pragma unroll
        for (int i = 0; i < 4; i++) {
            int idx = tid + i * 256;
            int n = idx >> 4, g = idx & 15;
            cp16(bs + n * RSTR64 + g * 4, BT + (size_t)n * DIMC + k0 + g * 4);
        }
    };

    const unsigned aOff = (unsigned)(((wm + (lane & 15)) * RSTR64 + (lane >> 4) * 4) * 4);
    const unsigned bOff = (unsigned)(A64_FL * 4 +
        ((wn + ((lane >> 4) << 3) + (lane & 7)) * RSTR64 + ((lane >> 3) & 1) * 4) * 4);
    const unsigned sb = smem_u32(sm);

    load_chunk(0, 0); CP_COMMIT();

#pragma unroll 1
    for (int c = 0; c < NCH64; c++) {
        const int s = c & 1;
        CP_WAIT0();
        __syncthreads();
        if (c + 1 < NCH64) {
            load_chunk(c + 1, s ^ 1);
            CP_COMMIT();
        }

        const unsigned stb = sb + (unsigned)(s * ST64_BYTES);
        const unsigned aA = stb + aOff;
        const unsigned bA = stb + bOff;
#pragma unroll
        for (int ks = 0; ks < 8; ks++) {
            unsigned a0[4], a1[4], b0[4], b1[4];
            ldsm4(a0, aA + ks * 32);
            ldsm4(a1, aA + 4352 + ks * 32);
            ldsm4(b0, bA + ks * 32);
            ldsm4(b1, bA + 4352 + ks * 32);
            mma_tf32(acc[0][0], a0, &b0[0]);
            mma_tf32(acc[0][1], a0, &b0[2]);
            mma_tf32(acc[0][2], a0, &b1[0]);
            mma_tf32(acc[0][3], a0, &b1[2]);
            mma_tf32(acc[1][0], a1, &b0[0]);
            mma_tf32(acc[1][1], a1, &b0[2]);
            mma_tf32(acc[1][2], a1, &b1[0]);
            mma_tf32(acc[1][3], a1, &b1[2]);
        }
    }

#pragma unroll
    for (int mi = 0; mi < 2; mi++) {
        const int row = by * BM + wm + mi * 16 + grp;
#pragma unroll
        for (int ni = 0; ni < 4; ni++) {
            const int col = wn + ni * 8 + 2 * ctg;
            *(float2*)(C + (size_t)row * ldc + col) =
                make_float2(acc[mi][ni][0], acc[mi][ni][1]);
            *(float2*)(C + (size_t)(row + 8) * ldc + col) =
                make_float2(acc[mi][ni][2], acc[mi][ni][3]);
        }
    }
}

__global__ __launch_bounds__(256, 3)
void tf32_qkv(const float* __restrict__ X,
              const float* __restrict__ WqT, const float* __restrict__ WkT,
              const float* __restrict__ WvT,
              float* __restrict__ Q, float* __restrict__ Ko, float* __restrict__ Vo)
{
    extern __shared__ float sm[];
    const int bx = blockIdx.x;
    const float* BT; float* C; int ld;
    if (bx < 16)      { BT = WqT + (size_t)bx * 64 * DIMC;        C = Q  + bx * 64;        ld = DIMC;  }
    else if (bx < 20) { BT = WkT + (size_t)(bx - 16) * 64 * DIMC; C = Ko + (bx - 16) * 64; ld = KVDIM; }
    else              { BT = WvT + (size_t)(bx - 20) * 64 * DIMC; C = Vo + (bx - 20) * 64; ld = KVDIM; }
    mma_tile32<true>(X, BT, C, ld, blockIdx.y, sm);   // rounded outputs for attention
}

__global__ __launch_bounds__(256, 2)
void tf32_wo(const float* __restrict__ Ac, const float* __restrict__ WoT,
             float* __restrict__ Out)
{
    extern __shared__ float sm[];
    mma_tile64(Ac, WoT + (size_t)blockIdx.x * 64 * DIMC, Out + blockIdx.x * 64,
               DIMC, blockIdx.y, sm);
}

// =================================================================
// Tensorized attention, 2 query heads per block (shared KV).
// Grid (64, 8), 256 threads, 103KB dyn smem.
// =================================================================
#define AT_QS 0
#define AT_KL 4352
#define AT_KG 10880
#define AT_VT 13056
#define AT_P  21504
#define ATTN_SMEM (25728 * 4)

__global__ __launch_bounds__(256)
void attn_mma(const float* __restrict__ Q, const float* __restrict__ K,
              const float* __restrict__ V, float* __restrict__ O)
{
    extern __shared__ float sm[];
    const int kvh = blockIdx.y >> 1;
    const int h0  = blockIdx.y * 2;
    const int q0  = blockIdx.x * TQ;
    const int tid = threadIdx.x, lane = tid & 31, warp = tid >> 5;
    const float4 z4 = make_float4(0.f, 0.f, 0.f, 0.f);

    for (int i = tid; i < 1024; i += 256) {
        int hh = i >> 9, rem = i & 511, q = rem >> 4, d4 = rem & 15;
        cp16(&sm[AT_QS + hh * 2176 + q * 68 + d4 * 4],
             &Q[(size_t)(q0 + q) * DIMC + (h0 + hh) * HD + d4 * 4]);
    }
    for (int i = tid; i < 1536; i += 256) {
        int r = i >> 4, d4 = i & 15;
        int key = q0 - 64 + r;
        cp16z(&sm[AT_KL + r * 68 + d4 * 4],
              &K[(size_t)max(key, 0) * KVDIM + kvh * HD + d4 * 4], key >= 0);
    }
    for (int i = tid; i < 512; i += 256) {
        int g = i >> 4, d4 = i & 15;
        cp16(&sm[AT_KG + g * 68 + d4 * 4],
             &K[(size_t)(g * WIN) * KVDIM + kvh * HD + d4 * 4]);
    }
    CP_COMMIT();

    for (int i = tid; i < 2048; i += 256) {
        int col = i >> 4, d4 = i & 15;
        int key; bool valid;
        if (col < 96) { key = q0 - 64 + col; valid = (key >= 0); }
        else          { key = (col - 96) * WIN; valid = true; }
        float4 v = valid ? *(const float4*)&V[(size_t)key * KVDIM + kvh * HD + d4 * 4] : z4;
        sm[AT_VT + (d4 * 4 + 0) * 132 + col] = v.x;
        sm[AT_VT + (d4 * 4 + 1) * 132 + col] = v.y;
        sm[AT_VT + (d4 * 4 + 2) * 132 + col] = v.z;
        sm[AT_VT + (d4 * 4 + 3) * 132 + col] = v.w;
    }
    CP_WAIT0();
    __syncthreads();

    const unsigned sb = smem_u32(sm);
    const int m0  = (warp >> 2) * 16;
    const int wnl = (warp & 3) * 24;
    const int wng = (warp & 3) * 8;
    const int ln  = lane & 15;
    const int grp = lane >> 2, ctg = lane & 3;

#pragma unroll 1
    for (int hh = 0; hh < 2; hh++) {
        const int h = h0 + hh;
        const float slope = exp2f(-0.5f * (float)(h + 1));

        {
            const unsigned aQ  = sb + (unsigned)((AT_QS + hh * 2176 + (m0 + ln) * 68 + (lane >> 4) * 4) * 4);
            const unsigned bKl = sb + (unsigned)((AT_KL + (wnl + ((lane >> 4) << 3) + (lane & 7)) * 68 + ((lane >> 3) & 1) * 4) * 4);
            const unsigned bK2 = sb + (unsigned)((AT_KL + (wnl + 16 + (ln & 7)) * 68 + ((ln >> 3) & 1) * 4) * 4);
            const unsigned bKg = sb + (unsigned)((AT_KG + (wng + (ln & 7)) * 68 + ((ln >> 3) & 1) * 4) * 4);

            float accl[3][4], accg[4];
#pragma unroll
            for (int f = 0; f < 3; f++)
#pragma unroll
                for (int r = 0; r < 4; r++) accl[f][r] = 0.f;
#pragma unroll
            for (int r = 0; r < 4; r++) accg[r] = 0.f;

#pragma unroll
            for (int ks = 0; ks < 8; ks++) {
                unsigned a[4], b01[4], b2[2], bg[2];
                ldsm4(a, aQ + ks * 32);
                ldsm4(b01, bKl + ks * 32);
                ldsm2(b2, bK2 + ks * 32);
                ldsm2(bg, bKg + ks * 32);
                mma_tf32(accl[0], a, &b01[0]);
                mma_tf32(accl[1], a, &b01[2]);
                mma_tf32(accl[2], a, b2);
                mma_tf32(accg, a, bg);
            }
            const int row = m0 + grp;
#pragma unroll
            for (int f = 0; f < 3; f++) {
                int col = wnl + f * 8 + 2 * ctg;
                *(float2*)&sm[AT_P + row * 132 + col]       = make_float2(accl[f][0], accl[f][1]);
                *(float2*)&sm[AT_P + (row + 8) * 132 + col] = make_float2(accl[f][2], accl[f][3]);
            }
            int colg = 96 + wng + 2 * ctg;
            *(float2*)&sm[AT_P + row * 132 + colg]       = make_float2(accg[0], accg[1]);
            *(float2*)&sm[AT_P + (row + 8) * 132 + colg] = make_float2(accg[2], accg[3]);
        }
        __syncthreads();

        for (int q = warp * 4; q < warp * 4 + 4; q++) {
            float l[3]; bool vld[3];
            float m = -3.0e38f;
#pragma unroll
            for (int t = 0; t < 3; t++) {
                int r = lane + t * 32;
                vld[t] = (r >= q) && (r <= q + 64) && (q0 - 64 + r >= 0);
                l[t] = vld[t] ? sm[AT_P + q * 132 + r] * SCALE + (float)(r - q - 64) * slope
                              : -3.0e38f;
                m = fmaxf(m, l[t]);
            }
#pragma unroll
            for (int o = 16; o; o >>= 1) m = fmaxf(m, __shfl_xor_sync(~0u, m, o));
            float e[3], sum = 0.f;
#pragma unroll
            for (int t = 0; t < 3; t++) {
                e[t] = vld[t] ? __expf(l[t] - m) : 0.f;
                sum += e[t];
            }
#pragma unroll
            for (int o = 16; o; o >>= 1) sum += __shfl_xor_sync(~0u, sum, o);
            float inv = 1.f / sum;
#pragma unroll
            for (int t = 0; t < 3; t++)
                sm[AT_P + q * 132 + lane + t * 32] = tf32r(e[t] * inv);

            float gl = sm[AT_P + q * 132 + 96 + lane] * SCALE;
            float mg = gl;
#pragma unroll
            for (int o = 16; o; o >>= 1) mg = fmaxf(mg, __shfl_xor_sync(~0u, mg, o));
            float ge = __expf(gl - mg);
            float gs = ge;
#pragma unroll
            for (int o = 16; o; o >>= 1) gs += __shfl_xor_sync(~0u, gs, o);
            sm[AT_P + q * 132 + 96 + lane] = tf32r(ge / gs);
        }
        __syncthreads();

        {
            const int n0 = (warp & 3) * 16;
            const unsigned aP = sb + (unsigned)((AT_P + (m0 + ln) * 132 + (lane >> 4) * 4) * 4);
            const unsigned bV = sb + (unsigned)((AT_VT + (n0 + ((lane >> 4) << 3) + (lane & 7)) * 132 + ((lane >> 3) & 1) * 4) * 4);

            float acco[2][4];
#pragma unroll
            for (int f = 0; f < 2; f++)
#pragma unroll
                for (int r = 0; r < 4; r++) acco[f][r] = 0.f;

#pragma unroll
            for (int ks = 0; ks < 16; ks++) {
                unsigned a[4], b[4];
                ldsm4(a, aP + ks * 32);
                ldsm4(b, bV + ks * 32);
                mma_tf32(acco[0], a, &b[0]);
                mma_tf32(acco[1], a, &b[2]);
            }

            const int row = m0 + grp;
#pragma unroll
            for (int f = 0; f < 2; f++) {
                int col = h * HD + n0 + f * 8 + 2 * ctg;
                *(float2*)&O[(size_t)(q0 + row) * DIMC + col] =
                    make_float2(acco[f][0], acco[f][1]);
                *(float2*)&O[(size_t)(q0 + row + 8) * DIMC + col] =
                    make_float2(acco[f][2], acco[f][3]);
            }
        }
        if (hh == 0) __syncthreads();
    }
}

// =================================================================
extern "C" void kernel_launch(void* const* d_in, const int* in_sizes, int n_in,
                              void* d_out, int out_size)
{
    const float* x  = (const float*)d_in[0];
    const float* Wq = (const float*)d_in[1];
    const float* Wk = (const float*)d_in[2];
    const float* Wv = (const float*)d_in[3];
    const float* Wo = (const float*)d_in[4];
    float* out = (float*)d_out;

    float *gQ, *gK, *gV, *gA, *gWqT, *gWkT, *gWvT, *gWoT;
    cudaGetSymbolAddress((void**)&gQ,  g_Q);
    cudaGetSymbolAddress((void**)&gK,  g_K);
    cudaGetSymbolAddress((void**)&gV,  g_V);
    cudaGetSymbolAddress((void**)&gA,  g_A);
    cudaGetSymbolAddress((void**)&gWqT, g_WqT);
    cudaGetSymbolAddress((void**)&gWkT, g_WkT);
    cudaGetSymbolAddress((void**)&gWvT, g_WvT);
    cudaGetSymbolAddress((void**)&gWoT, g_WoT);

    cudaFuncSetAttribute(tf32_qkv, cudaFuncAttributeMaxDynamicSharedMemorySize, QKV_SMEM);
    cudaFuncSetAttribute(tf32_wo,  cudaFuncAttributeMaxDynamicSharedMemorySize, WO_SMEM);
    cudaFuncSetAttribute(attn_mma, cudaFuncAttributeMaxDynamicSharedMemorySize, ATTN_SMEM);

    cvt_w<<<2560, 256>>>(Wq, Wk, Wv, Wo, gWqT, gWkT, gWvT, gWoT);
    tf32_qkv<<<dim3(24, 16), 256, QKV_SMEM>>>(x, gWqT, gWkT, gWvT, gQ, gK, gV);
    attn_mma<<<dim3(SEQ / TQ, HEADS / 2), 256, ATTN_SMEM>>>(gQ, gK, gV, gA);
    tf32_wo<<<dim3(16, 16), 256, WO_SMEM>>>(gA, gWoT, out);
}